// round 11
// baseline (speedup 1.0000x reference)
#include <cuda_runtime.h>
#include <cuda_fp16.h>
#include <cstdint>

#define NTOK (8*4096)      // B*S tokens
#define DM   768

// ---------------- scratch (static device globals; no allocations) ----------------
__device__ float  g_Y  [(size_t)NTOK*DM];   // projections, padded 760->768
__device__ __half g_zh [(size_t)NTOK*DM];   // scrambled attention output, fp16
__device__ __half g_W1hi[DM*DM];
__device__ __half g_Wohi[DM*DM];
__device__ float  g_b1[DM];

// ---------------- small helpers ----------------
__device__ __forceinline__ uint32_t smem_u32(const void* p){
    return (uint32_t)__cvta_generic_to_shared(p);
}
__device__ __forceinline__ void cpa16(uint32_t s, const void* g){
    asm volatile("cp.async.cg.shared.global [%0], [%1], 16;\n" :: "r"(s), "l"(g));
}
__device__ __forceinline__ void cpa_commit(){ asm volatile("cp.async.commit_group;\n"::); }
__device__ __forceinline__ void cpa_wait0(){ asm volatile("cp.async.wait_group 0;\n"::); }
__device__ __forceinline__ void cpa_wait1(){ asm volatile("cp.async.wait_group 1;\n"::); }
__device__ __forceinline__ void cpa_wait2(){ asm volatile("cp.async.wait_group 2;\n"::); }

__device__ __forceinline__ void ldsm4(uint32_t& r0, uint32_t& r1, uint32_t& r2, uint32_t& r3, uint32_t a){
    asm volatile("ldmatrix.sync.aligned.m8n8.x4.shared.b16 {%0,%1,%2,%3}, [%4];\n"
                 : "=r"(r0),"=r"(r1),"=r"(r2),"=r"(r3) : "r"(a));
}
__device__ __forceinline__ void ldsm4t(uint32_t& r0, uint32_t& r1, uint32_t& r2, uint32_t& r3, uint32_t a){
    asm volatile("ldmatrix.sync.aligned.m8n8.x4.trans.shared.b16 {%0,%1,%2,%3}, [%4];\n"
                 : "=r"(r0),"=r"(r1),"=r"(r2),"=r"(r3) : "r"(a));
}
__device__ __forceinline__ void mma16816(float* c, const uint32_t* a, const uint32_t* b){
    asm volatile("mma.sync.aligned.m16n8k16.row.col.f32.f16.f16.f32 "
                 "{%0,%1,%2,%3},{%4,%5,%6,%7},{%8,%9},{%0,%1,%2,%3};\n"
                 : "+f"(c[0]),"+f"(c[1]),"+f"(c[2]),"+f"(c[3])
                 : "r"(a[0]),"r"(a[1]),"r"(a[2]),"r"(a[3]),"r"(b[0]),"r"(b[1]));
}
__device__ __forceinline__ uint32_t packh2(float2 v){
    __half2 h = __float22half2_rn(v);
    return *(uint32_t*)&h;
}

// ---------------- weight prep: pack W1 (concat of 6 projections, padded to 768) ----------------
__global__ void k_pack_weights(const float* __restrict__ Waq, const float* __restrict__ Wbq,
                               const float* __restrict__ Wak, const float* __restrict__ Wbk,
                               const float* __restrict__ Wav, const float* __restrict__ Wbv,
                               const float* __restrict__ baq, const float* __restrict__ bbq,
                               const float* __restrict__ bak, const float* __restrict__ bbk,
                               const float* __restrict__ bav, const float* __restrict__ bbv,
                               const float* __restrict__ Wout)
{
    int idx = blockIdx.x*blockDim.x + threadIdx.x;
    if (idx >= DM*DM) return;
    int k = idx / DM, n = idx % DM;
    // column layout: [A_Q 0..72 | B_Q 72..456 | A_K 456..480 | B_K 480..608 | A_V 608..632 | B_V 632..760 | pad]
    float w;
    if      (n < 72)  w = Waq[k*72  + n];
    else if (n < 456) w = Wbq[k*384 + (n-72)];
    else if (n < 480) w = Wak[k*24  + (n-456)];
    else if (n < 608) w = Wbk[k*128 + (n-480)];
    else if (n < 632) w = Wav[k*24  + (n-608)];
    else if (n < 760) w = Wbv[k*128 + (n-632)];
    else              w = 0.0f;
    g_W1hi[idx] = __float2half_rn(w);
    g_Wohi[idx] = __float2half_rn(Wout[idx]);

    if (k == 0){
        float bb;
        if      (n < 72)  bb = baq[n];
        else if (n < 456) bb = bbq[n-72];
        else if (n < 480) bb = bak[n-456];
        else if (n < 608) bb = bbk[n-480];
        else if (n < 632) bb = bav[n-608];
        else if (n < 760) bb = bbv[n-632];
        else              bb = 0.0f;
        g_b1[n] = bb;
    }
}

// ================= GEMM common geometry =================
// Tiles 128x128x32, 8 warps (4m x 2n), warp = 32x64, mma m16n8k16.
// 4-stage cp.async ring in dynamic smem, prefetch distance 3, one barrier/iter.
#define BM 128
#define BN 128
#define BK 32
#define BSTRIDE 136
#define B_SZ (BK*BSTRIDE*2)            // 8704 B

// ---------------- stage-1 GEMM with fused fp32->fp16 A conversion ----------------
// A tile staged as fp32 (128 x 32, stride 36 floats); converted to fp16 in the
// smem->register stage (LDS.64 + cvt pack). B fp16 via ldmatrix as before.
#define AF_STRIDE 36
#define AF_SZ (BM*AF_STRIDE*4)         // 18432 B
#define SMEM_G1 (4*(AF_SZ + B_SZ))     // 108544 B

__global__ __launch_bounds__(256, 2) void k_gemm_f32a(
    const float* __restrict__ A0, const __half* __restrict__ B0,
    const float* __restrict__ bias, float* __restrict__ C)
{
    extern __shared__ __align__(16) char smem[];
    float* Afs = (float*)smem;                       // 4 A stages (fp32)
    const uint32_t sB = smem_u32(smem) + 4*AF_SZ;    // 4 B stages (fp16)

    const int tid  = threadIdx.x;
    const int warp = tid >> 5, lane = tid & 31;
    const int wm = warp & 3, wn = warp >> 2;
    const int n0 = blockIdx.x * BN;     // n fastest (6)
    const int m0 = blockIdx.y * BM;
    const int niter = 24;   // K=768, BK=32

    float acc[2][8][4];
    #pragma unroll
    for (int i=0;i<2;i++)
        #pragma unroll
        for (int j=0;j<8;j++)
            #pragma unroll
            for (int q=0;q<4;q++) acc[i][j][q] = 0.0f;

    const int lrow  = (lane & 7) + ((lane >> 3) & 1) * 8;
    const int lcol8 = (lane >> 4) * 8;
    const int gr4   = lane >> 2;        // 0..7
    const int cl2   = (lane & 3)*2;

    auto load_tile = [&](int it){
        const int st = it & 3;
        const int kk = it * BK;
        const uint32_t aBase = smem_u32(smem) + st*AF_SZ;
        const uint32_t bBase = sB + st*B_SZ;
        #pragma unroll
        for (int j=0;j<4;j++){   // A: 1024 chunks of 16B (4 floats)
            int id = tid + j*256;
            int r = id >> 3, c = id & 7;
            cpa16(aBase + (uint32_t)(r*AF_STRIDE + c*4)*4, A0 + (size_t)(m0 + r)*DM + kk + c*4);
        }
        #pragma unroll
        for (int j=0;j<2;j++){   // B: 512 chunks of 16B
            int id = tid + j*256;
            int r = id >> 4, c = id & 15;    // 32 rows x 16 chunks
            cpa16(bBase + (uint32_t)(r*BSTRIDE + c*8)*2, B0 + (size_t)(kk + r)*DM + n0 + c*8);
        }
    };

    load_tile(0); cpa_commit();
    load_tile(1); cpa_commit();
    load_tile(2); cpa_commit();

    for (int it = 0; it < niter; it++){
        if      (it < niter-2) cpa_wait2();
        else if (it == niter-2) cpa_wait1();
        else                    cpa_wait0();
        __syncthreads();
        if (it + 3 < niter){ load_tile(it+3); cpa_commit(); }

        const int st = it & 3;
        const float* Af = Afs + st*(AF_SZ/4);
        const uint32_t bBase = sB + st*B_SZ;

        #pragma unroll
        for (int ks=0; ks<2; ks++){
            const int k0 = ks*16;
            uint32_t a[2][4], b[8][2];
            #pragma unroll
            for (int i=0;i<2;i++){
                int r0 = wm*32 + i*16 + gr4;
                float2 v00 = *(float2*)(Af + (r0  )*AF_STRIDE + k0 + cl2);
                float2 v10 = *(float2*)(Af + (r0+8)*AF_STRIDE + k0 + cl2);
                float2 v01 = *(float2*)(Af + (r0  )*AF_STRIDE + k0 + cl2 + 8);
                float2 v11 = *(float2*)(Af + (r0+8)*AF_STRIDE + k0 + cl2 + 8);
                a[i][0] = packh2(v00);
                a[i][1] = packh2(v10);
                a[i][2] = packh2(v01);
                a[i][3] = packh2(v11);
            }
            #pragma unroll
            for (int jp=0;jp<4;jp++){
                uint32_t ad = bBase + (uint32_t)((k0 + lrow)*BSTRIDE + wn*64 + jp*16 + lcol8)*2;
                uint32_t r0,r1,r2,r3;
                ldsm4t(r0,r1,r2,r3, ad);
                b[2*jp][0]=r0;   b[2*jp][1]=r1;
                b[2*jp+1][0]=r2; b[2*jp+1][1]=r3;
            }
            #pragma unroll
            for (int i=0;i<2;i++)
                #pragma unroll
                for (int j=0;j<8;j++)
                    mma16816(acc[i][j], a[i], b[j]);
        }
    }

    // epilogue: bias + fp32 store
    #pragma unroll
    for (int i=0;i<2;i++){
        int grow = m0 + wm*32 + i*16 + (lane >> 2);
        #pragma unroll
        for (int j=0;j<8;j++){
            int gcol = n0 + wn*64 + j*8 + (lane & 3)*2;
            float bb0 = bias[gcol], bb1 = bias[gcol+1];
            float2 v0 = make_float2(acc[i][j][0] + bb0, acc[i][j][1] + bb1);
            float2 v1 = make_float2(acc[i][j][2] + bb0, acc[i][j][3] + bb1);
            *(float2*)(C + (size_t)grow*DM + gcol)     = v0;
            *(float2*)(C + (size_t)(grow+8)*DM + gcol) = v1;
        }
    }
}

// ---------------- stage-2 GEMM: fp16 A (g_zh) ----------------
#define ASTRIDE 40
#define A_SZ (BM*ASTRIDE*2)            // 10240 B
#define SMEM_G2 (4*(A_SZ + B_SZ))      // 75776 B

__global__ __launch_bounds__(256, 2) void k_gemm(
    const __half* __restrict__ A0, const __half* __restrict__ B0,
    const float* __restrict__ bias, float* __restrict__ C)
{
    extern __shared__ __align__(16) char smem[];
    const uint32_t sA = smem_u32(smem);                 // 4 A stages
    const uint32_t sB = sA + 4*A_SZ;                    // 4 B stages

    const int tid  = threadIdx.x;
    const int warp = tid >> 5, lane = tid & 31;
    const int wm = warp & 3, wn = warp >> 2;
    const int n0 = blockIdx.x * BN;     // n fastest (6)
    const int m0 = blockIdx.y * BM;
    const int niter = 24;   // K=768, BK=32

    float acc[2][8][4];
    #pragma unroll
    for (int i=0;i<2;i++)
        #pragma unroll
        for (int j=0;j<8;j++)
            #pragma unroll
            for (int q=0;q<4;q++) acc[i][j][q] = 0.0f;

    const int lrow  = (lane & 7) + ((lane >> 3) & 1) * 8;
    const int lcol8 = (lane >> 4) * 8;

    auto load_tile = [&](int it){
        const int st = it & 3;
        const int kk = it * BK;
        const uint32_t aBase = sA + st*A_SZ;
        const uint32_t bBase = sB + st*B_SZ;
        #pragma unroll
        for (int j=0;j<2;j++){
            int id = tid + j*256;
            int r = id >> 2, c = id & 3;     // 128 rows x 4 chunks of 16B
            cpa16(aBase + (uint32_t)(r*ASTRIDE + c*8)*2, A0 + (size_t)(m0 + r)*DM + kk + c*8);
        }
        #pragma unroll
        for (int j=0;j<2;j++){
            int id = tid + j*256;
            int r = id >> 4, c = id & 15;    // 32 rows x 16 chunks
            cpa16(bBase + (uint32_t)(r*BSTRIDE + c*8)*2, B0 + (size_t)(kk + r)*DM + n0 + c*8);
        }
    };

    load_tile(0); cpa_commit();
    load_tile(1); cpa_commit();
    load_tile(2); cpa_commit();

    for (int it = 0; it < niter; it++){
        if      (it < niter-2) cpa_wait2();
        else if (it == niter-2) cpa_wait1();
        else                    cpa_wait0();
        __syncthreads();
        if (it + 3 < niter){ load_tile(it+3); cpa_commit(); }

        const int st = it & 3;
        const uint32_t aBase = sA + st*A_SZ;
        const uint32_t bBase = sB + st*B_SZ;

        #pragma unroll
        for (int ks=0; ks<2; ks++){
            const int k0 = ks*16;
            uint32_t a[2][4], b[8][2];
            #pragma unroll
            for (int i=0;i<2;i++){
                uint32_t ad = aBase + (uint32_t)((wm*32 + i*16 + lrow)*ASTRIDE + k0 + lcol8)*2;
                ldsm4(a[i][0], a[i][1], a[i][2], a[i][3], ad);
            }
            #pragma unroll
            for (int jp=0;jp<4;jp++){
                uint32_t ad = bBase + (uint32_t)((k0 + lrow)*BSTRIDE + wn*64 + jp*16 + lcol8)*2;
                uint32_t r0,r1,r2,r3;
                ldsm4t(r0,r1,r2,r3, ad);
                b[2*jp][0]=r0;   b[2*jp][1]=r1;
                b[2*jp+1][0]=r2; b[2*jp+1][1]=r3;
            }
            #pragma unroll
            for (int i=0;i<2;i++)
                #pragma unroll
                for (int j=0;j<8;j++)
                    mma16816(acc[i][j], a[i], b[j]);
        }
    }

    // epilogue: bias + fp32 store
    #pragma unroll
    for (int i=0;i<2;i++){
        int grow = m0 + wm*32 + i*16 + (lane >> 2);
        #pragma unroll
        for (int j=0;j<8;j++){
            int gcol = n0 + wn*64 + j*8 + (lane & 3)*2;
            float bb0 = bias[gcol], bb1 = bias[gcol+1];
            float2 v0 = make_float2(acc[i][j][0] + bb0, acc[i][j][1] + bb1);
            float2 v1 = make_float2(acc[i][j][2] + bb0, acc[i][j][3] + bb1);
            *(float2*)(C + (size_t)grow*DM + gcol)     = v0;
            *(float2*)(C + (size_t)(grow+8)*DM + gcol) = v1;
        }
    }
}

// ---------------- middle: rope + rank-contracted head attention, per token ----------------
// warp = 1 token; lane owns d = {2*lane, 2*lane+1}
__global__ __launch_bounds__(256) void k_middle(const float* __restrict__ rope){
    __shared__ float Ys[8][DM];
    __shared__ float Cs[8][24];
    const int w = threadIdx.x >> 5, lane = threadIdx.x & 31;
    const int t = blockIdx.x*8 + w;
    const int s = t & 4095, b = t >> 12;

    {   // stage Y row
        const float4* src = (const float4*)(g_Y + (size_t)t*DM);
        float4* dst = (float4*)Ys[w];
        #pragma unroll
        for (int i=0;i<6;i++) dst[lane + 32*i] = src[lane + 32*i];
    }
    __syncwarp();

    const int d0 = lane*2;
    float2 rp = *(const float2*)(rope + s*64 + d0);

    float bq[6][2], bk[2][2], bv[2][2];
    #pragma unroll
    for (int r=0;r<6;r++){
        float2 v = *(float2*)&Ys[w][72 + r*64 + d0];
        bq[r][0] = v.x * rp.x; bq[r][1] = v.y * rp.y;
    }
    #pragma unroll
    for (int p=0;p<2;p++){
        float2 v = *(float2*)&Ys[w][480 + p*64 + d0];
        bk[p][0] = v.x * rp.x; bk[p][1] = v.y * rp.y;
        float2 u = *(float2*)&Ys[w][632 + p*64 + d0];
        bv[p][0] = u.x; bv[p][1] = u.y;
    }

    float G[12];
    #pragma unroll
    for (int r=0;r<6;r++){
        #pragma unroll
        for (int p=0;p<2;p++){
            float v = bq[r][0]*bk[p][0] + bq[r][1]*bk[p][1];
            #pragma unroll
            for (int o=16;o>0;o>>=1) v += __shfl_xor_sync(0xffffffffu, v, o);
            G[r*2+p] = v * 0.125f;   // 1/sqrt(64)
        }
    }

    if (lane < 24){
        const int h = lane >> 1, gb = (lane & 1)*6;
        float aq[6];
        #pragma unroll
        for (int r=0;r<6;r++) aq[r] = Ys[w][r*12 + h];
        float sc[6];
        #pragma unroll
        for (int gg=0;gg<6;gg++){
            int g = gb + gg;
            float ak0 = Ys[w][456 + g], ak1 = Ys[w][468 + g];
            float accv = 0.0f;
            #pragma unroll
            for (int r=0;r<6;r++) accv += aq[r]*(ak0*G[2*r] + ak1*G[2*r+1]);
            sc[gg] = accv;
        }
        float mx = sc[0];
        #pragma unroll
        for (int gg=1;gg<6;gg++) mx = fmaxf(mx, sc[gg]);
        mx = fmaxf(mx, __shfl_xor_sync(0x00ffffffu, mx, 1));
        float e[6], sum = 0.0f;
        #pragma unroll
        for (int gg=0;gg<6;gg++){ e[gg] = __expf(sc[gg]-mx); sum += e[gg]; }
        sum += __shfl_xor_sync(0x00ffffffu, sum, 1);
        float inv = 1.0f/sum;
        float c0 = 0.0f, c1 = 0.0f;
        #pragma unroll
        for (int gg=0;gg<6;gg++){
            int g = gb + gg;
            float a = e[gg]*inv;
            c0 += a*Ys[w][608 + g];   // A_V[0][g]
            c1 += a*Ys[w][620 + g];   // A_V[1][g]
        }
        c0 += __shfl_xor_sync(0x00ffffffu, c0, 1);
        c1 += __shfl_xor_sync(0x00ffffffu, c1, 1);
        if ((lane & 1) == 0){ Cs[w][2*h] = c0; Cs[w][2*h+1] = c1; }
    }
    __syncwarp();

    #pragma unroll
    for (int h=0;h<12;h++){
        float c0 = Cs[w][2*h], c1 = Cs[w][2*h+1];
        float z0 = c0*bv[0][0] + c1*bv[1][0];
        float z1 = c0*bv[0][1] + c1*bv[1][1];
        int u = h*4096 + s;
        size_t dst = ((size_t)(b*4096 + u/12))*DM + (u%12)*64 + d0;
        __half2 hv; hv.x = __float2half_rn(z0); hv.y = __float2half_rn(z1);
        *(__half2*)(g_zh + dst) = hv;
    }
}

// ---------------- launch ----------------
extern "C" void kernel_launch(void* const* d_in, const int* in_sizes, int n_in,
                              void* d_out, int out_size)
{
    const float* x    = (const float*)d_in[0];
    const float* rope = (const float*)d_in[1];
    const float* Waq  = (const float*)d_in[2];
    const float* baq  = (const float*)d_in[3];
    const float* Wbq  = (const float*)d_in[4];
    const float* bbq  = (const float*)d_in[5];
    const float* Wak  = (const float*)d_in[6];
    const float* bak  = (const float*)d_in[7];
    const float* Wbk  = (const float*)d_in[8];
    const float* bbk  = (const float*)d_in[9];
    const float* Wav  = (const float*)d_in[10];
    const float* bav  = (const float*)d_in[11];
    const float* Wbv  = (const float*)d_in[12];
    const float* bbv  = (const float*)d_in[13];
    const float* Wout = (const float*)d_in[14];
    const float* bout = (const float*)d_in[15];

    void *p_Y, *p_zh, *p_W1hi, *p_Wohi, *p_b1;
    cudaGetSymbolAddress(&p_Y,    g_Y);
    cudaGetSymbolAddress(&p_zh,   g_zh);
    cudaGetSymbolAddress(&p_W1hi, g_W1hi);
    cudaGetSymbolAddress(&p_Wohi, g_Wohi);
    cudaGetSymbolAddress(&p_b1,   g_b1);

    cudaFuncSetAttribute(k_gemm_f32a, cudaFuncAttributeMaxDynamicSharedMemorySize, SMEM_G1);
    cudaFuncSetAttribute(k_gemm,      cudaFuncAttributeMaxDynamicSharedMemorySize, SMEM_G2);

    k_pack_weights<<<(DM*DM + 255)/256, 256>>>(Waq,Wbq,Wak,Wbk,Wav,Wbv,
                                               baq,bbq,bak,bbk,bav,bbv, Wout);

    // stage 1: Y = fp16(x) @ W1_h + b1, with fused fp32->fp16 conversion of x
    k_gemm_f32a<<<dim3(6,256), 256, SMEM_G1>>>(x, (const __half*)p_W1hi,
                                               (const float*)p_b1, (float*)p_Y);

    k_middle<<<NTOK/8, 256>>>(rope);

    // stage 2: out = z @ Wout_h + b_out
    k_gemm<<<dim3(6,256), 256, SMEM_G2>>>((const __half*)p_zh, (const __half*)p_Wohi,
                                          bout, (float*)d_out);
}

// round 13
// speedup vs baseline: 1.1267x; 1.1267x over previous
#include <cuda_runtime.h>
#include <cuda_fp16.h>
#include <cstdint>

#define NTOK (8*4096)      // B*S tokens
#define DM   768

// ---------------- scratch (static device globals; no allocations) ----------------
__device__ __half g_xhi[(size_t)NTOK*DM];
__device__ float  g_Y  [(size_t)NTOK*DM];   // projections, padded 760->768
__device__ __half g_zh [(size_t)NTOK*DM];   // scrambled attention output, fp16
__device__ __half g_W1hi[DM*DM];
__device__ __half g_Wohi[DM*DM];
__device__ float  g_b1[DM];

// ---------------- small helpers ----------------
__device__ __forceinline__ uint32_t smem_u32(const void* p){
    return (uint32_t)__cvta_generic_to_shared(p);
}
__device__ __forceinline__ void cpa16(uint32_t s, const void* g){
    asm volatile("cp.async.cg.shared.global [%0], [%1], 16;\n" :: "r"(s), "l"(g));
}
__device__ __forceinline__ void cpa_commit(){ asm volatile("cp.async.commit_group;\n"::); }
__device__ __forceinline__ void cpa_wait0(){ asm volatile("cp.async.wait_group 0;\n"::); }
__device__ __forceinline__ void cpa_wait1(){ asm volatile("cp.async.wait_group 1;\n"::); }
__device__ __forceinline__ void cpa_wait2(){ asm volatile("cp.async.wait_group 2;\n"::); }

__device__ __forceinline__ void ldsm4(uint32_t& r0, uint32_t& r1, uint32_t& r2, uint32_t& r3, uint32_t a){
    asm volatile("ldmatrix.sync.aligned.m8n8.x4.shared.b16 {%0,%1,%2,%3}, [%4];\n"
                 : "=r"(r0),"=r"(r1),"=r"(r2),"=r"(r3) : "r"(a));
}
__device__ __forceinline__ void ldsm4t(uint32_t& r0, uint32_t& r1, uint32_t& r2, uint32_t& r3, uint32_t a){
    asm volatile("ldmatrix.sync.aligned.m8n8.x4.trans.shared.b16 {%0,%1,%2,%3}, [%4];\n"
                 : "=r"(r0),"=r"(r1),"=r"(r2),"=r"(r3) : "r"(a));
}
__device__ __forceinline__ void mma16816(float* c, const uint32_t* a, const uint32_t* b){
    asm volatile("mma.sync.aligned.m16n8k16.row.col.f32.f16.f16.f32 "
                 "{%0,%1,%2,%3},{%4,%5,%6,%7},{%8,%9},{%0,%1,%2,%3};\n"
                 : "+f"(c[0]),"+f"(c[1]),"+f"(c[2]),"+f"(c[3])
                 : "r"(a[0]),"r"(a[1]),"r"(a[2]),"r"(a[3]),"r"(b[0]),"r"(b[1]));
}

// ---------------- weight prep: pack W1 (concat of 6 projections, padded to 768) ----------------
__global__ void k_pack_weights(const float* __restrict__ Waq, const float* __restrict__ Wbq,
                               const float* __restrict__ Wak, const float* __restrict__ Wbk,
                               const float* __restrict__ Wav, const float* __restrict__ Wbv,
                               const float* __restrict__ baq, const float* __restrict__ bbq,
                               const float* __restrict__ bak, const float* __restrict__ bbk,
                               const float* __restrict__ bav, const float* __restrict__ bbv,
                               const float* __restrict__ Wout)
{
    int idx = blockIdx.x*blockDim.x + threadIdx.x;
    if (idx >= DM*DM) return;
    int k = idx / DM, n = idx % DM;
    // column layout: [A_Q 0..72 | B_Q 72..456 | A_K 456..480 | B_K 480..608 | A_V 608..632 | B_V 632..760 | pad]
    float w;
    if      (n < 72)  w = Waq[k*72  + n];
    else if (n < 456) w = Wbq[k*384 + (n-72)];
    else if (n < 480) w = Wak[k*24  + (n-456)];
    else if (n < 608) w = Wbk[k*128 + (n-480)];
    else if (n < 632) w = Wav[k*24  + (n-608)];
    else if (n < 760) w = Wbv[k*128 + (n-632)];
    else              w = 0.0f;
    g_W1hi[idx] = __float2half_rn(w);
    g_Wohi[idx] = __float2half_rn(Wout[idx]);

    if (k == 0){
        float bb;
        if      (n < 72)  bb = baq[n];
        else if (n < 456) bb = bbq[n-72];
        else if (n < 480) bb = bak[n-456];
        else if (n < 608) bb = bbk[n-480];
        else if (n < 632) bb = bav[n-608];
        else if (n < 760) bb = bbv[n-632];
        else              bb = 0.0f;
        g_b1[n] = bb;
    }
}

// ---------------- x -> fp16 ----------------
__global__ void k_convert_x(const float* __restrict__ x){
    int i = blockIdx.x*blockDim.x + threadIdx.x;
    const int n4 = NTOK*DM/4;
    if (i >= n4) return;
    float4 v = ((const float4*)x)[i];
    __half2 a; a.x = __float2half_rn(v.x); a.y = __float2half_rn(v.y);
    __half2 b; b.x = __float2half_rn(v.z); b.y = __float2half_rn(v.w);
    ((__half2*)g_xhi)[2*i]   = a;
    ((__half2*)g_xhi)[2*i+1] = b;
}

// ---------------- fp16 GEMM: C[M=32768][768] = A @ B + bias ----------------
// Tile 128x128x32, 512 threads = 16 warps (4m x 4n), warp tile 32x32, mma m16n8k16.
// 4-stage cp.async ring in dynamic smem, prefetch distance 3, one barrier/iter.
// Low per-warp register count (acc=32) so 2 CTAs/SM -> 32 warps/SM for latency hiding.
#define BM 128
#define BN 128
#define BK 32
#define ASTRIDE 40
#define BSTRIDE 136
#define A_SZ (BM*ASTRIDE*2)            // 10240 B
#define B_SZ (BK*BSTRIDE*2)            // 8704 B
#define NSTG 4
#define SMEM_GEMM (NSTG*(A_SZ + B_SZ)) // 75776 B

__global__ __launch_bounds__(512, 2) void k_gemm(
    const __half* __restrict__ A0, const __half* __restrict__ B0,
    const float* __restrict__ bias, float* __restrict__ C)
{
    extern __shared__ __align__(16) char smem[];
    const uint32_t sA = smem_u32(smem);                 // 4 A stages
    const uint32_t sB = sA + NSTG*A_SZ;                 // 4 B stages

    const int tid  = threadIdx.x;
    const int warp = tid >> 5, lane = tid & 31;
    const int wm = warp & 3, wn = warp >> 2;            // 4 x 4 warp grid
    const int n0 = blockIdx.x * BN;                     // n fastest (6)
    const int m0 = blockIdx.y * BM;
    const int niter = 24;   // K=768, BK=32

    float acc[2][4][4];
    #pragma unroll
    for (int i=0;i<2;i++)
        #pragma unroll
        for (int j=0;j<4;j++)
            #pragma unroll
            for (int q=0;q<4;q++) acc[i][j][q] = 0.0f;

    const int lrow  = (lane & 7) + ((lane >> 3) & 1) * 8;
    const int lcol8 = (lane >> 4) * 8;

    auto load_tile = [&](int it){
        const int st = it & 3;
        const int kk = it * BK;
        const uint32_t aBase = sA + st*A_SZ;
        const uint32_t bBase = sB + st*B_SZ;
        {   // A: 512 chunks of 16B (128 rows x 4 chunks)
            int r = tid >> 2, c = tid & 3;
            cpa16(aBase + (uint32_t)(r*ASTRIDE + c*8)*2, A0 + (size_t)(m0 + r)*DM + kk + c*8);
        }
        {   // B: 512 chunks of 16B (32 rows x 16 chunks)
            int r = tid >> 4, c = tid & 15;
            cpa16(bBase + (uint32_t)(r*BSTRIDE + c*8)*2, B0 + (size_t)(kk + r)*DM + n0 + c*8);
        }
    };

    load_tile(0); cpa_commit();
    load_tile(1); cpa_commit();
    load_tile(2); cpa_commit();

    for (int it = 0; it < niter; it++){
        // FIFO retirement: allow up to 2 newer groups to stay pending.
        if      (it < niter-2) cpa_wait2();
        else if (it == niter-2) cpa_wait1();
        else                    cpa_wait0();
        __syncthreads();   // publishes tile it; frees buf (it-1)&3 (reuse distance 3)
        if (it + 3 < niter){ load_tile(it+3); cpa_commit(); }

        const int st = it & 3;
        const uint32_t aBase = sA + st*A_SZ;
        const uint32_t bBase = sB + st*B_SZ;

        #pragma unroll
        for (int ks=0; ks<2; ks++){
            const int k0 = ks*16;
            uint32_t a[2][4], b[4][2];
            #pragma unroll
            for (int i=0;i<2;i++){
                uint32_t ad = aBase + (uint32_t)((wm*32 + i*16 + lrow)*ASTRIDE + k0 + lcol8)*2;
                ldsm4(a[i][0], a[i][1], a[i][2], a[i][3], ad);
            }
            #pragma unroll
            for (int jp=0;jp<2;jp++){
                uint32_t ad = bBase + (uint32_t)((k0 + lrow)*BSTRIDE + wn*32 + jp*16 + lcol8)*2;
                uint32_t r0,r1,r2,r3;
                ldsm4t(r0,r1,r2,r3, ad);
                b[2*jp][0]=r0;   b[2*jp][1]=r1;
                b[2*jp+1][0]=r2; b[2*jp+1][1]=r3;
            }
            #pragma unroll
            for (int i=0;i<2;i++)
                #pragma unroll
                for (int j=0;j<4;j++)
                    mma16816(acc[i][j], a[i], b[j]);
        }
    }

    // epilogue: bias + fp32 store
    #pragma unroll
    for (int i=0;i<2;i++){
        int grow = m0 + wm*32 + i*16 + (lane >> 2);
        #pragma unroll
        for (int j=0;j<4;j++){
            int gcol = n0 + wn*32 + j*8 + (lane & 3)*2;
            float bb0 = bias[gcol], bb1 = bias[gcol+1];
            float2 v0 = make_float2(acc[i][j][0] + bb0, acc[i][j][1] + bb1);
            float2 v1 = make_float2(acc[i][j][2] + bb0, acc[i][j][3] + bb1);
            *(float2*)(C + (size_t)grow*DM + gcol)     = v0;
            *(float2*)(C + (size_t)(grow+8)*DM + gcol) = v1;
        }
    }
}

// ---------------- middle: rope + rank-contracted head attention, per token ----------------
// warp = 1 token; lane owns d = {2*lane, 2*lane+1}
__global__ __launch_bounds__(256) void k_middle(const float* __restrict__ rope){
    __shared__ float Ys[8][DM];
    __shared__ float Cs[8][24];
    const int w = threadIdx.x >> 5, lane = threadIdx.x & 31;
    const int t = blockIdx.x*8 + w;
    const int s = t & 4095, b = t >> 12;

    {   // stage Y row
        const float4* src = (const float4*)(g_Y + (size_t)t*DM);
        float4* dst = (float4*)Ys[w];
        #pragma unroll
        for (int i=0;i<6;i++) dst[lane + 32*i] = src[lane + 32*i];
    }
    __syncwarp();

    const int d0 = lane*2;
    float2 rp = *(const float2*)(rope + s*64 + d0);

    float bq[6][2], bk[2][2], bv[2][2];
    #pragma unroll
    for (int r=0;r<6;r++){
        float2 v = *(float2*)&Ys[w][72 + r*64 + d0];
        bq[r][0] = v.x * rp.x; bq[r][1] = v.y * rp.y;
    }
    #pragma unroll
    for (int p=0;p<2;p++){
        float2 v = *(float2*)&Ys[w][480 + p*64 + d0];
        bk[p][0] = v.x * rp.x; bk[p][1] = v.y * rp.y;
        float2 u = *(float2*)&Ys[w][632 + p*64 + d0];
        bv[p][0] = u.x; bv[p][1] = u.y;
    }

    float G[12];
    #pragma unroll
    for (int r=0;r<6;r++){
        #pragma unroll
        for (int p=0;p<2;p++){
            float v = bq[r][0]*bk[p][0] + bq[r][1]*bk[p][1];
            #pragma unroll
            for (int o=16;o>0;o>>=1) v += __shfl_xor_sync(0xffffffffu, v, o);
            G[r*2+p] = v * 0.125f;   // 1/sqrt(64)
        }
    }

    if (lane < 24){
        const int h = lane >> 1, gb = (lane & 1)*6;
        float aq[6];
        #pragma unroll
        for (int r=0;r<6;r++) aq[r] = Ys[w][r*12 + h];
        float sc[6];
        #pragma unroll
        for (int gg=0;gg<6;gg++){
            int g = gb + gg;
            float ak0 = Ys[w][456 + g], ak1 = Ys[w][468 + g];
            float accv = 0.0f;
            #pragma unroll
            for (int r=0;r<6;r++) accv += aq[r]*(ak0*G[2*r] + ak1*G[2*r+1]);
            sc[gg] = accv;
        }
        float mx = sc[0];
        #pragma unroll
        for (int gg=1;gg<6;gg++) mx = fmaxf(mx, sc[gg]);
        mx = fmaxf(mx, __shfl_xor_sync(0x00ffffffu, mx, 1));
        float e[6], sum = 0.0f;
        #pragma unroll
        for (int gg=0;gg<6;gg++){ e[gg] = __expf(sc[gg]-mx); sum += e[gg]; }
        sum += __shfl_xor_sync(0x00ffffffu, sum, 1);
        float inv = 1.0f/sum;
        float c0 = 0.0f, c1 = 0.0f;
        #pragma unroll
        for (int gg=0;gg<6;gg++){
            int g = gb + gg;
            float a = e[gg]*inv;
            c0 += a*Ys[w][608 + g];   // A_V[0][g]
            c1 += a*Ys[w][620 + g];   // A_V[1][g]
        }
        c0 += __shfl_xor_sync(0x00ffffffu, c0, 1);
        c1 += __shfl_xor_sync(0x00ffffffu, c1, 1);
        if ((lane & 1) == 0){ Cs[w][2*h] = c0; Cs[w][2*h+1] = c1; }
    }
    __syncwarp();

    #pragma unroll
    for (int h=0;h<12;h++){
        float c0 = Cs[w][2*h], c1 = Cs[w][2*h+1];
        float z0 = c0*bv[0][0] + c1*bv[1][0];
        float z1 = c0*bv[0][1] + c1*bv[1][1];
        int u = h*4096 + s;
        size_t dst = ((size_t)(b*4096 + u/12))*DM + (u%12)*64 + d0;
        __half2 hv; hv.x = __float2half_rn(z0); hv.y = __float2half_rn(z1);
        *(__half2*)(g_zh + dst) = hv;
    }
}

// ---------------- launch ----------------
extern "C" void kernel_launch(void* const* d_in, const int* in_sizes, int n_in,
                              void* d_out, int out_size)
{
    const float* x    = (const float*)d_in[0];
    const float* rope = (const float*)d_in[1];
    const float* Waq  = (const float*)d_in[2];
    const float* baq  = (const float*)d_in[3];
    const float* Wbq  = (const float*)d_in[4];
    const float* bbq  = (const float*)d_in[5];
    const float* Wak  = (const float*)d_in[6];
    const float* bak  = (const float*)d_in[7];
    const float* Wbk  = (const float*)d_in[8];
    const float* bbk  = (const float*)d_in[9];
    const float* Wav  = (const float*)d_in[10];
    const float* bav  = (const float*)d_in[11];
    const float* Wbv  = (const float*)d_in[12];
    const float* bbv  = (const float*)d_in[13];
    const float* Wout = (const float*)d_in[14];
    const float* bout = (const float*)d_in[15];

    void *p_xhi, *p_Y, *p_zh, *p_W1hi, *p_Wohi, *p_b1;
    cudaGetSymbolAddress(&p_xhi,  g_xhi);
    cudaGetSymbolAddress(&p_Y,    g_Y);
    cudaGetSymbolAddress(&p_zh,   g_zh);
    cudaGetSymbolAddress(&p_W1hi, g_W1hi);
    cudaGetSymbolAddress(&p_Wohi, g_Wohi);
    cudaGetSymbolAddress(&p_b1,   g_b1);

    cudaFuncSetAttribute(k_gemm, cudaFuncAttributeMaxDynamicSharedMemorySize, SMEM_GEMM);

    k_pack_weights<<<(DM*DM + 255)/256, 256>>>(Waq,Wbq,Wak,Wbk,Wav,Wbv,
                                               baq,bbq,bak,bbk,bav,bbv, Wout);
    k_convert_x<<<(NTOK*DM/4 + 255)/256, 256>>>(x);

    // stage 1: Y = x_h @ W1_h + b1   (single fp16 phase)
    k_gemm<<<dim3(6,256), 512, SMEM_GEMM>>>((const __half*)p_xhi, (const __half*)p_W1hi,
                                            (const float*)p_b1, (float*)p_Y);

    k_middle<<<NTOK/8, 256>>>(rope);

    // stage 2: out = z @ Wout_h + b_out   (single fp16 phase)
    k_gemm<<<dim3(6,256), 512, SMEM_GEMM>>>((const __half*)p_zh, (const __half*)p_Wohi,
                                            bout, (float*)d_out);
}

// round 15
// speedup vs baseline: 1.1409x; 1.0126x over previous
#include <cuda_runtime.h>
#include <cuda_fp16.h>
#include <cstdint>

#define NTOK (8*4096)      // B*S tokens
#define DM   768

// ---------------- scratch (static device globals; no allocations) ----------------
__device__ __half g_xhi[(size_t)NTOK*DM];
__device__ float  g_Y  [(size_t)NTOK*DM];   // projections, padded 760->768
__device__ __half g_zh [(size_t)NTOK*DM];   // scrambled attention output, fp16
__device__ __half g_W1hi[DM*DM];
__device__ __half g_Wohi[DM*DM];
__device__ float  g_b1[DM];

// ---------------- small helpers ----------------
__device__ __forceinline__ uint32_t smem_u32(const void* p){
    return (uint32_t)__cvta_generic_to_shared(p);
}
__device__ __forceinline__ void cpa16(uint32_t s, const void* g){
    asm volatile("cp.async.cg.shared.global [%0], [%1], 16;\n" :: "r"(s), "l"(g));
}
__device__ __forceinline__ void cpa_commit(){ asm volatile("cp.async.commit_group;\n"::); }
__device__ __forceinline__ void cpa_wait0(){ asm volatile("cp.async.wait_group 0;\n"::); }
__device__ __forceinline__ void cpa_wait1(){ asm volatile("cp.async.wait_group 1;\n"::); }

__device__ __forceinline__ void ldsm4(uint32_t& r0, uint32_t& r1, uint32_t& r2, uint32_t& r3, uint32_t a){
    asm volatile("ldmatrix.sync.aligned.m8n8.x4.shared.b16 {%0,%1,%2,%3}, [%4];\n"
                 : "=r"(r0),"=r"(r1),"=r"(r2),"=r"(r3) : "r"(a));
}
__device__ __forceinline__ void ldsm4t(uint32_t& r0, uint32_t& r1, uint32_t& r2, uint32_t& r3, uint32_t a){
    asm volatile("ldmatrix.sync.aligned.m8n8.x4.trans.shared.b16 {%0,%1,%2,%3}, [%4];\n"
                 : "=r"(r0),"=r"(r1),"=r"(r2),"=r"(r3) : "r"(a));
}
__device__ __forceinline__ void mma16816(float* c, const uint32_t* a, const uint32_t* b){
    asm volatile("mma.sync.aligned.m16n8k16.row.col.f32.f16.f16.f32 "
                 "{%0,%1,%2,%3},{%4,%5,%6,%7},{%8,%9},{%0,%1,%2,%3};\n"
                 : "+f"(c[0]),"+f"(c[1]),"+f"(c[2]),"+f"(c[3])
                 : "r"(a[0]),"r"(a[1]),"r"(a[2]),"r"(a[3]),"r"(b[0]),"r"(b[1]));
}

// ---------------- fused prep: pack weights (blocks 0..2303) + convert x (rest) ----------------
#define PACK_BLOCKS 2304                         // DM*DM/256
#define CONV_BLOCKS (NTOK*DM/4/256)              // 24576

__global__ void k_prep(const float* __restrict__ x,
                       const float* __restrict__ Waq, const float* __restrict__ Wbq,
                       const float* __restrict__ Wak, const float* __restrict__ Wbk,
                       const float* __restrict__ Wav, const float* __restrict__ Wbv,
                       const float* __restrict__ baq, const float* __restrict__ bbq,
                       const float* __restrict__ bak, const float* __restrict__ bbk,
                       const float* __restrict__ bav, const float* __restrict__ bbv,
                       const float* __restrict__ Wout)
{
    int bid = blockIdx.x;
    if (bid < PACK_BLOCKS){
        int idx = bid*blockDim.x + threadIdx.x;
        if (idx >= DM*DM) return;
        int k = idx / DM, n = idx % DM;
        // cols: [A_Q 0..72 | B_Q 72..456 | A_K 456..480 | B_K 480..608 | A_V 608..632 | B_V 632..760 | pad]
        float w;
        if      (n < 72)  w = Waq[k*72  + n];
        else if (n < 456) w = Wbq[k*384 + (n-72)];
        else if (n < 480) w = Wak[k*24  + (n-456)];
        else if (n < 608) w = Wbk[k*128 + (n-480)];
        else if (n < 632) w = Wav[k*24  + (n-608)];
        else if (n < 760) w = Wbv[k*128 + (n-632)];
        else              w = 0.0f;
        g_W1hi[idx] = __float2half_rn(w);
        g_Wohi[idx] = __float2half_rn(Wout[idx]);

        if (k == 0){
            float bb;
            if      (n < 72)  bb = baq[n];
            else if (n < 456) bb = bbq[n-72];
            else if (n < 480) bb = bak[n-456];
            else if (n < 608) bb = bbk[n-480];
            else if (n < 632) bb = bav[n-608];
            else if (n < 760) bb = bbv[n-632];
            else              bb = 0.0f;
            g_b1[n] = bb;
        }
    } else {
        int i = (bid - PACK_BLOCKS)*blockDim.x + threadIdx.x;
        const int n4 = NTOK*DM/4;
        if (i >= n4) return;
        float4 v = ((const float4*)x)[i];
        __half2 a; a.x = __float2half_rn(v.x); a.y = __float2half_rn(v.y);
        __half2 b; b.x = __float2half_rn(v.z); b.y = __float2half_rn(v.w);
        ((__half2*)g_xhi)[2*i]   = a;
        ((__half2*)g_xhi)[2*i+1] = b;
    }
}

// ---------------- fp16 GEMM: C[M=32768][768] = A @ B + bias ----------------
// Tile 128x128x64, 512 threads = 16 warps (4m x 4n), warp tile 32x32, mma m16n8k16.
// 3-stage cp.async ring (BK=64 slabs), prefetch distance 2, ONE barrier per iter.
// 12 iters (vs 24 at BK=32) -> half the barrier/wait overhead.
#define BM 128
#define BN 128
#define BK 64
#define ASTRIDE 72                      // 64 halves + 8 pad
#define BSTRIDE 136
#define A_SZ (BM*ASTRIDE*2)             // 18432 B
#define B_SZ (BK*BSTRIDE*2)             // 17408 B
#define NSTG 3
#define SMEM_GEMM (NSTG*(A_SZ + B_SZ))  // 107520 B

__global__ __launch_bounds__(512, 2) void k_gemm(
    const __half* __restrict__ A0, const __half* __restrict__ B0,
    const float* __restrict__ bias, float* __restrict__ C)
{
    extern __shared__ __align__(16) char smem[];
    const uint32_t sA = smem_u32(smem);                 // 3 A stages
    const uint32_t sB = sA + NSTG*A_SZ;                 // 3 B stages

    const int tid  = threadIdx.x;
    const int warp = tid >> 5, lane = tid & 31;
    const int wm = warp & 3, wn = warp >> 2;            // 4 x 4 warp grid
    const int n0 = blockIdx.x * BN;                     // n fastest (6)
    const int m0 = blockIdx.y * BM;
    const int niter = 12;   // K=768, BK=64

    float acc[2][4][4];
    #pragma unroll
    for (int i=0;i<2;i++)
        #pragma unroll
        for (int j=0;j<4;j++)
            #pragma unroll
            for (int q=0;q<4;q++) acc[i][j][q] = 0.0f;

    const int lrow  = (lane & 7) + ((lane >> 3) & 1) * 8;
    const int lcol8 = (lane >> 4) * 8;

    auto load_tile = [&](int it){
        const int st = it % 3;
        const int kk = it * BK;
        const uint32_t aBase = sA + st*A_SZ;
        const uint32_t bBase = sB + st*B_SZ;
        #pragma unroll
        for (int j=0;j<2;j++){   // A: 1024 chunks of 16B (128 rows x 8 chunks)
            int id = tid + j*512;
            int r = id >> 3, c = id & 7;
            cpa16(aBase + (uint32_t)(r*ASTRIDE + c*8)*2, A0 + (size_t)(m0 + r)*DM + kk + c*8);
        }
        #pragma unroll
        for (int j=0;j<2;j++){   // B: 1024 chunks of 16B (64 rows x 16 chunks)
            int id = tid + j*512;
            int r = id >> 4, c = id & 15;
            cpa16(bBase + (uint32_t)(r*BSTRIDE + c*8)*2, B0 + (size_t)(kk + r)*DM + n0 + c*8);
        }
    };

    load_tile(0); cpa_commit();
    load_tile(1); cpa_commit();

    for (int it = 0; it < niter; it++){
        if (it < niter-1) cpa_wait1(); else cpa_wait0();
        __syncthreads();   // publishes tile it; frees stage (it+2)%3 (tile it-1)
        if (it + 2 < niter){ load_tile(it+2); cpa_commit(); }

        const int st = it % 3;
        const uint32_t aBase = sA + st*A_SZ;
        const uint32_t bBase = sB + st*B_SZ;

        #pragma unroll
        for (int ks=0; ks<4; ks++){
            const int k0 = ks*16;
            uint32_t a[2][4], b[4][2];
            #pragma unroll
            for (int i=0;i<2;i++){
                uint32_t ad = aBase + (uint32_t)((wm*32 + i*16 + lrow)*ASTRIDE + k0 + lcol8)*2;
                ldsm4(a[i][0], a[i][1], a[i][2], a[i][3], ad);
            }
            #pragma unroll
            for (int jp=0;jp<2;jp++){
                uint32_t ad = bBase + (uint32_t)((k0 + lrow)*BSTRIDE + wn*32 + jp*16 + lcol8)*2;
                uint32_t r0,r1,r2,r3;
                ldsm4t(r0,r1,r2,r3, ad);
                b[2*jp][0]=r0;   b[2*jp][1]=r1;
                b[2*jp+1][0]=r2; b[2*jp+1][1]=r3;
            }
            #pragma unroll
            for (int i=0;i<2;i++)
                #pragma unroll
                for (int j=0;j<4;j++)
                    mma16816(acc[i][j], a[i], b[j]);
        }
    }

    // epilogue: bias + fp32 store
    #pragma unroll
    for (int i=0;i<2;i++){
        int grow = m0 + wm*32 + i*16 + (lane >> 2);
        #pragma unroll
        for (int j=0;j<4;j++){
            int gcol = n0 + wn*32 + j*8 + (lane & 3)*2;
            float bb0 = bias[gcol], bb1 = bias[gcol+1];
            float2 v0 = make_float2(acc[i][j][0] + bb0, acc[i][j][1] + bb1);
            float2 v1 = make_float2(acc[i][j][2] + bb0, acc[i][j][3] + bb1);
            *(float2*)(C + (size_t)grow*DM + gcol)     = v0;
            *(float2*)(C + (size_t)(grow+8)*DM + gcol) = v1;
        }
    }
}

// ---------------- middle: rope + rank-contracted head attention, per token ----------------
// warp = 1 token; lane owns d = {2*lane, 2*lane+1}
__global__ __launch_bounds__(256) void k_middle(const float* __restrict__ rope){
    __shared__ float Ys[8][DM];
    __shared__ float Cs[8][24];
    const int w = threadIdx.x >> 5, lane = threadIdx.x & 31;
    const int t = blockIdx.x*8 + w;
    const int s = t & 4095, b = t >> 12;

    {   // stage Y row
        const float4* src = (const float4*)(g_Y + (size_t)t*DM);
        float4* dst = (float4*)Ys[w];
        #pragma unroll
        for (int i=0;i<6;i++) dst[lane + 32*i] = src[lane + 32*i];
    }
    __syncwarp();

    const int d0 = lane*2;
    float2 rp = *(const float2*)(rope + s*64 + d0);

    float bq[6][2], bk[2][2], bv[2][2];
    #pragma unroll
    for (int r=0;r<6;r++){
        float2 v = *(float2*)&Ys[w][72 + r*64 + d0];
        bq[r][0] = v.x * rp.x; bq[r][1] = v.y * rp.y;
    }
    #pragma unroll
    for (int p=0;p<2;p++){
        float2 v = *(float2*)&Ys[w][480 + p*64 + d0];
        bk[p][0] = v.x * rp.x; bk[p][1] = v.y * rp.y;
        float2 u = *(float2*)&Ys[w][632 + p*64 + d0];
        bv[p][0] = u.x; bv[p][1] = u.y;
    }

    float G[12];
    #pragma unroll
    for (int r=0;r<6;r++){
        #pragma unroll
        for (int p=0;p<2;p++){
            float v = bq[r][0]*bk[p][0] + bq[r][1]*bk[p][1];
            #pragma unroll
            for (int o=16;o>0;o>>=1) v += __shfl_xor_sync(0xffffffffu, v, o);
            G[r*2+p] = v * 0.125f;   // 1/sqrt(64)
        }
    }

    if (lane < 24){
        const int h = lane >> 1, gb = (lane & 1)*6;
        float aq[6];
        #pragma unroll
        for (int r=0;r<6;r++) aq[r] = Ys[w][r*12 + h];
        float sc[6];
        #pragma unroll
        for (int gg=0;gg<6;gg++){
            int g = gb + gg;
            float ak0 = Ys[w][456 + g], ak1 = Ys[w][468 + g];
            float accv = 0.0f;
            #pragma unroll
            for (int r=0;r<6;r++) accv += aq[r]*(ak0*G[2*r] + ak1*G[2*r+1]);
            sc[gg] = accv;
        }
        float mx = sc[0];
        #pragma unroll
        for (int gg=1;gg<6;gg++) mx = fmaxf(mx, sc[gg]);
        mx = fmaxf(mx, __shfl_xor_sync(0x00ffffffu, mx, 1));
        float e[6], sum = 0.0f;
        #pragma unroll
        for (int gg=0;gg<6;gg++){ e[gg] = __expf(sc[gg]-mx); sum += e[gg]; }
        sum += __shfl_xor_sync(0x00ffffffu, sum, 1);
        float inv = 1.0f/sum;
        float c0 = 0.0f, c1 = 0.0f;
        #pragma unroll
        for (int gg=0;gg<6;gg++){
            int g = gb + gg;
            float a = e[gg]*inv;
            c0 += a*Ys[w][608 + g];   // A_V[0][g]
            c1 += a*Ys[w][620 + g];   // A_V[1][g]
        }
        c0 += __shfl_xor_sync(0x00ffffffu, c0, 1);
        c1 += __shfl_xor_sync(0x00ffffffu, c1, 1);
        if ((lane & 1) == 0){ Cs[w][2*h] = c0; Cs[w][2*h+1] = c1; }
    }
    __syncwarp();

    #pragma unroll
    for (int h=0;h<12;h++){
        float c0 = Cs[w][2*h], c1 = Cs[w][2*h+1];
        float z0 = c0*bv[0][0] + c1*bv[1][0];
        float z1 = c0*bv[0][1] + c1*bv[1][1];
        int u = h*4096 + s;
        size_t dst = ((size_t)(b*4096 + u/12))*DM + (u%12)*64 + d0;
        __half2 hv; hv.x = __float2half_rn(z0); hv.y = __float2half_rn(z1);
        *(__half2*)(g_zh + dst) = hv;
    }
}

// ---------------- launch ----------------
extern "C" void kernel_launch(void* const* d_in, const int* in_sizes, int n_in,
                              void* d_out, int out_size)
{
    const float* x    = (const float*)d_in[0];
    const float* rope = (const float*)d_in[1];
    const float* Waq  = (const float*)d_in[2];
    const float* baq  = (const float*)d_in[3];
    const float* Wbq  = (const float*)d_in[4];
    const float* bbq  = (const float*)d_in[5];
    const float* Wak  = (const float*)d_in[6];
    const float* bak  = (const float*)d_in[7];
    const float* Wbk  = (const float*)d_in[8];
    const float* bbk  = (const float*)d_in[9];
    const float* Wav  = (const float*)d_in[10];
    const float* bav  = (const float*)d_in[11];
    const float* Wbv  = (const float*)d_in[12];
    const float* bbv  = (const float*)d_in[13];
    const float* Wout = (const float*)d_in[14];
    const float* bout = (const float*)d_in[15];

    void *p_xhi, *p_Y, *p_zh, *p_W1hi, *p_Wohi, *p_b1;
    cudaGetSymbolAddress(&p_xhi,  g_xhi);
    cudaGetSymbolAddress(&p_Y,    g_Y);
    cudaGetSymbolAddress(&p_zh,   g_zh);
    cudaGetSymbolAddress(&p_W1hi, g_W1hi);
    cudaGetSymbolAddress(&p_Wohi, g_Wohi);
    cudaGetSymbolAddress(&p_b1,   g_b1);

    cudaFuncSetAttribute(k_gemm, cudaFuncAttributeMaxDynamicSharedMemorySize, SMEM_GEMM);

    // fused weight pack + x conversion
    k_prep<<<PACK_BLOCKS + CONV_BLOCKS, 256>>>(x, Waq,Wbq,Wak,Wbk,Wav,Wbv,
                                               baq,bbq,bak,bbk,bav,bbv, Wout);

    // stage 1: Y = x_h @ W1_h + b1   (single fp16 phase)
    k_gemm<<<dim3(6,256), 512, SMEM_GEMM>>>((const __half*)p_xhi, (const __half*)p_W1hi,
                                            (const float*)p_b1, (float*)p_Y);

    k_middle<<<NTOK/8, 256>>>(rope);

    // stage 2: out = z @ Wout_h + b_out   (single fp16 phase)
    k_gemm<<<dim3(6,256), 512, SMEM_GEMM>>>((const __half*)p_zh, (const __half*)p_Wohi,
                                            bout, (float*)d_out);
}

// round 17
// speedup vs baseline: 1.1482x; 1.0064x over previous
#include <cuda_runtime.h>
#include <cuda_fp16.h>
#include <cstdint>

#define NTOK (8*4096)      // B*S tokens
#define DM   768

// ---------------- scratch (static device globals; no allocations) ----------------
__device__ __half g_xhi[(size_t)NTOK*DM];
__device__ float  g_Y  [(size_t)NTOK*DM];   // projections, padded 760->768
__device__ __half g_zh [(size_t)NTOK*DM];   // scrambled attention output, fp16
__device__ __half g_W1hi[DM*DM];
__device__ __half g_Wohi[DM*DM];
__device__ float  g_b1[DM];

// ---------------- small helpers ----------------
__device__ __forceinline__ uint32_t smem_u32(const void* p){
    return (uint32_t)__cvta_generic_to_shared(p);
}
__device__ __forceinline__ void cpa16(uint32_t s, const void* g){
    asm volatile("cp.async.cg.shared.global [%0], [%1], 16;\n" :: "r"(s), "l"(g));
}
__device__ __forceinline__ void cpa_commit(){ asm volatile("cp.async.commit_group;\n"::); }
__device__ __forceinline__ void cpa_wait0(){ asm volatile("cp.async.wait_group 0;\n"::); }
__device__ __forceinline__ void cpa_wait1(){ asm volatile("cp.async.wait_group 1;\n"::); }

__device__ __forceinline__ void ldsm4(uint32_t& r0, uint32_t& r1, uint32_t& r2, uint32_t& r3, uint32_t a){
    asm volatile("ldmatrix.sync.aligned.m8n8.x4.shared.b16 {%0,%1,%2,%3}, [%4];\n"
                 : "=r"(r0),"=r"(r1),"=r"(r2),"=r"(r3) : "r"(a));
}
__device__ __forceinline__ void ldsm4t(uint32_t& r0, uint32_t& r1, uint32_t& r2, uint32_t& r3, uint32_t a){
    asm volatile("ldmatrix.sync.aligned.m8n8.x4.trans.shared.b16 {%0,%1,%2,%3}, [%4];\n"
                 : "=r"(r0),"=r"(r1),"=r"(r2),"=r"(r3) : "r"(a));
}
__device__ __forceinline__ void mma16816(float* c, const uint32_t* a, const uint32_t* b){
    asm volatile("mma.sync.aligned.m16n8k16.row.col.f32.f16.f16.f32 "
                 "{%0,%1,%2,%3},{%4,%5,%6,%7},{%8,%9},{%0,%1,%2,%3};\n"
                 : "+f"(c[0]),"+f"(c[1]),"+f"(c[2]),"+f"(c[3])
                 : "r"(a[0]),"r"(a[1]),"r"(a[2]),"r"(a[3]),"r"(b[0]),"r"(b[1]));
}

// ---------------- fused prep: pack weights (blocks 0..2303) + convert x (rest) ----------------
#define PACK_BLOCKS 2304                         // DM*DM/256
#define CONV_BLOCKS (NTOK*DM/4/256)              // 24576

__global__ void k_prep(const float* __restrict__ x,
                       const float* __restrict__ Waq, const float* __restrict__ Wbq,
                       const float* __restrict__ Wak, const float* __restrict__ Wbk,
                       const float* __restrict__ Wav, const float* __restrict__ Wbv,
                       const float* __restrict__ baq, const float* __restrict__ bbq,
                       const float* __restrict__ bak, const float* __restrict__ bbk,
                       const float* __restrict__ bav, const float* __restrict__ bbv,
                       const float* __restrict__ Wout)
{
    int bid = blockIdx.x;
    if (bid < PACK_BLOCKS){
        int idx = bid*blockDim.x + threadIdx.x;
        if (idx >= DM*DM) return;
        int k = idx / DM, n = idx % DM;
        // cols: [A_Q 0..72 | B_Q 72..456 | A_K 456..480 | B_K 480..608 | A_V 608..632 | B_V 632..760 | pad]
        float w;
        if      (n < 72)  w = Waq[k*72  + n];
        else if (n < 456) w = Wbq[k*384 + (n-72)];
        else if (n < 480) w = Wak[k*24  + (n-456)];
        else if (n < 608) w = Wbk[k*128 + (n-480)];
        else if (n < 632) w = Wav[k*24  + (n-608)];
        else if (n < 760) w = Wbv[k*128 + (n-632)];
        else              w = 0.0f;
        g_W1hi[idx] = __float2half_rn(w);
        g_Wohi[idx] = __float2half_rn(Wout[idx]);

        if (k == 0){
            float bb;
            if      (n < 72)  bb = baq[n];
            else if (n < 456) bb = bbq[n-72];
            else if (n < 480) bb = bak[n-456];
            else if (n < 608) bb = bbk[n-480];
            else if (n < 632) bb = bav[n-608];
            else if (n < 760) bb = bbv[n-632];
            else              bb = 0.0f;
            g_b1[n] = bb;
        }
    } else {
        int i = (bid - PACK_BLOCKS)*blockDim.x + threadIdx.x;
        const int n4 = NTOK*DM/4;
        if (i >= n4) return;
        float4 v = ((const float4*)x)[i];
        __half2 a; a.x = __float2half_rn(v.x); a.y = __float2half_rn(v.y);
        __half2 b; b.x = __float2half_rn(v.z); b.y = __float2half_rn(v.w);
        ((__half2*)g_xhi)[2*i]   = a;
        ((__half2*)g_xhi)[2*i+1] = b;
    }
}

// ---------------- fp16 GEMM: C[M=32768][768] = A @ B + bias ----------------
// Tile 128x128x64, 512 threads = 16 warps (4m x 4n), warp tile 32x32, mma m16n8k16.
// 3-stage cp.async ring (BK=64 slabs), prefetch distance 2, ONE barrier per iter.
// M-blocks processed in REVERSE so this kernel reads its producer's freshest
// (still-L2-resident) output first (prep->gemm1 on xhi, middle->gemm2 on zh).
#define BM 128
#define BN 128
#define BK 64
#define ASTRIDE 72                      // 64 halves + 8 pad
#define BSTRIDE 136
#define A_SZ (BM*ASTRIDE*2)             // 18432 B
#define B_SZ (BK*BSTRIDE*2)             // 17408 B
#define NSTG 3
#define SMEM_GEMM (NSTG*(A_SZ + B_SZ))  // 107520 B

__global__ __launch_bounds__(512, 2) void k_gemm(
    const __half* __restrict__ A0, const __half* __restrict__ B0,
    const float* __restrict__ bias, float* __restrict__ C)
{
    extern __shared__ __align__(16) char smem[];
    const uint32_t sA = smem_u32(smem);                 // 3 A stages
    const uint32_t sB = sA + NSTG*A_SZ;                 // 3 B stages

    const int tid  = threadIdx.x;
    const int warp = tid >> 5, lane = tid & 31;
    const int wm = warp & 3, wn = warp >> 2;            // 4 x 4 warp grid
    const int n0 = blockIdx.x * BN;                     // n fastest (6)
    const int m0 = ((int)gridDim.y - 1 - (int)blockIdx.y) * BM;   // reversed m order
    const int niter = 12;   // K=768, BK=64

    float acc[2][4][4];
    #pragma unroll
    for (int i=0;i<2;i++)
        #pragma unroll
        for (int j=0;j<4;j++)
            #pragma unroll
            for (int q=0;q<4;q++) acc[i][j][q] = 0.0f;

    const int lrow  = (lane & 7) + ((lane >> 3) & 1) * 8;
    const int lcol8 = (lane >> 4) * 8;

    auto load_tile = [&](int it){
        const int st = it % 3;
        const int kk = it * BK;
        const uint32_t aBase = sA + st*A_SZ;
        const uint32_t bBase = sB + st*B_SZ;
        #pragma unroll
        for (int j=0;j<2;j++){   // A: 1024 chunks of 16B (128 rows x 8 chunks)
            int id = tid + j*512;
            int r = id >> 3, c = id & 7;
            cpa16(aBase + (uint32_t)(r*ASTRIDE + c*8)*2, A0 + (size_t)(m0 + r)*DM + kk + c*8);
        }
        #pragma unroll
        for (int j=0;j<2;j++){   // B: 1024 chunks of 16B (64 rows x 16 chunks)
            int id = tid + j*512;
            int r = id >> 4, c = id & 15;
            cpa16(bBase + (uint32_t)(r*BSTRIDE + c*8)*2, B0 + (size_t)(kk + r)*DM + n0 + c*8);
        }
    };

    load_tile(0); cpa_commit();
    load_tile(1); cpa_commit();

    for (int it = 0; it < niter; it++){
        if (it < niter-1) cpa_wait1(); else cpa_wait0();
        __syncthreads();   // publishes tile it; frees stage (it+2)%3 (tile it-1)
        if (it + 2 < niter){ load_tile(it+2); cpa_commit(); }

        const int st = it % 3;
        const uint32_t aBase = sA + st*A_SZ;
        const uint32_t bBase = sB + st*B_SZ;

        #pragma unroll
        for (int ks=0; ks<4; ks++){
            const int k0 = ks*16;
            uint32_t a[2][4], b[4][2];
            #pragma unroll
            for (int i=0;i<2;i++){
                uint32_t ad = aBase + (uint32_t)((wm*32 + i*16 + lrow)*ASTRIDE + k0 + lcol8)*2;
                ldsm4(a[i][0], a[i][1], a[i][2], a[i][3], ad);
            }
            #pragma unroll
            for (int jp=0;jp<2;jp++){
                uint32_t ad = bBase + (uint32_t)((k0 + lrow)*BSTRIDE + wn*32 + jp*16 + lcol8)*2;
                uint32_t r0,r1,r2,r3;
                ldsm4t(r0,r1,r2,r3, ad);
                b[2*jp][0]=r0;   b[2*jp][1]=r1;
                b[2*jp+1][0]=r2; b[2*jp+1][1]=r3;
            }
            #pragma unroll
            for (int i=0;i<2;i++)
                #pragma unroll
                for (int j=0;j<4;j++)
                    mma16816(acc[i][j], a[i], b[j]);
        }
    }

    // epilogue: bias + fp32 store
    #pragma unroll
    for (int i=0;i<2;i++){
        int grow = m0 + wm*32 + i*16 + (lane >> 2);
        #pragma unroll
        for (int j=0;j<4;j++){
            int gcol = n0 + wn*32 + j*8 + (lane & 3)*2;
            float bb0 = bias[gcol], bb1 = bias[gcol+1];
            float2 v0 = make_float2(acc[i][j][0] + bb0, acc[i][j][1] + bb1);
            float2 v1 = make_float2(acc[i][j][2] + bb0, acc[i][j][3] + bb1);
            *(float2*)(C + (size_t)grow*DM + gcol)     = v0;
            *(float2*)(C + (size_t)(grow+8)*DM + gcol) = v1;
        }
    }
}

// ---------------- middle: rope + rank-contracted head attention, per token ----------------
// warp = 1 token; lane owns d = {2*lane, 2*lane+1}
// Token order kept ASCENDING: gemm1 (reversed) finishes by writing low-m Y,
// so low tokens are the L2-resident ones when this kernel starts.
__global__ __launch_bounds__(256) void k_middle(const float* __restrict__ rope){
    __shared__ float Ys[8][DM];
    __shared__ float Cs[8][24];
    const int w = threadIdx.x >> 5, lane = threadIdx.x & 31;
    const int t = blockIdx.x*8 + w;
    const int s = t & 4095, b = t >> 12;

    {   // stage Y row
        const float4* src = (const float4*)(g_Y + (size_t)t*DM);
        float4* dst = (float4*)Ys[w];
        #pragma unroll
        for (int i=0;i<6;i++) dst[lane + 32*i] = src[lane + 32*i];
    }
    __syncwarp();

    const int d0 = lane*2;
    float2 rp = *(const float2*)(rope + s*64 + d0);

    float bq[6][2], bk[2][2], bv[2][2];
    #pragma unroll
    for (int r=0;r<6;r++){
        float2 v = *(float2*)&Ys[w][72 + r*64 + d0];
        bq[r][0] = v.x * rp.x; bq[r][1] = v.y * rp.y;
    }
    #pragma unroll
    for (int p=0;p<2;p++){
        float2 v = *(float2*)&Ys[w][480 + p*64 + d0];
        bk[p][0] = v.x * rp.x; bk[p][1] = v.y * rp.y;
        float2 u = *(float2*)&Ys[w][632 + p*64 + d0];
        bv[p][0] = u.x; bv[p][1] = u.y;
    }

    float G[12];
    #pragma unroll
    for (int r=0;r<6;r++){
        #pragma unroll
        for (int p=0;p<2;p++){
            float v = bq[r][0]*bk[p][0] + bq[r][1]*bk[p][1];
            #pragma unroll
            for (int o=16;o>0;o>>=1) v += __shfl_xor_sync(0xffffffffu, v, o);
            G[r*2+p] = v * 0.125f;   // 1/sqrt(64)
        }
    }

    if (lane < 24){
        const int h = lane >> 1, gb = (lane & 1)*6;
        float aq[6];
        #pragma unroll
        for (int r=0;r<6;r++) aq[r] = Ys[w][r*12 + h];
        float sc[6];
        #pragma unroll
        for (int gg=0;gg<6;gg++){
            int g = gb + gg;
            float ak0 = Ys[w][456 + g], ak1 = Ys[w][468 + g];
            float accv = 0.0f;
            #pragma unroll
            for (int r=0;r<6;r++) accv += aq[r]*(ak0*G[2*r] + ak1*G[2*r+1]);
            sc[gg] = accv;
        }
        float mx = sc[0];
        #pragma unroll
        for (int gg=1;gg<6;gg++) mx = fmaxf(mx, sc[gg]);
        mx = fmaxf(mx, __shfl_xor_sync(0x00ffffffu, mx, 1));
        float e[6], sum = 0.0f;
        #pragma unroll
        for (int gg=0;gg<6;gg++){ e[gg] = __expf(sc[gg]-mx); sum += e[gg]; }
        sum += __shfl_xor_sync(0x00ffffffu, sum, 1);
        float inv = 1.0f/sum;
        float c0 = 0.0f, c1 = 0.0f;
        #pragma unroll
        for (int gg=0;gg<6;gg++){
            int g = gb + gg;
            float a = e[gg]*inv;
            c0 += a*Ys[w][608 + g];   // A_V[0][g]
            c1 += a*Ys[w][620 + g];   // A_V[1][g]
        }
        c0 += __shfl_xor_sync(0x00ffffffu, c0, 1);
        c1 += __shfl_xor_sync(0x00ffffffu, c1, 1);
        if ((lane & 1) == 0){ Cs[w][2*h] = c0; Cs[w][2*h+1] = c1; }
    }
    __syncwarp();

    #pragma unroll
    for (int h=0;h<12;h++){
        float c0 = Cs[w][2*h], c1 = Cs[w][2*h+1];
        float z0 = c0*bv[0][0] + c1*bv[1][0];
        float z1 = c0*bv[0][1] + c1*bv[1][1];
        int u = h*4096 + s;
        size_t dst = ((size_t)(b*4096 + u/12))*DM + (u%12)*64 + d0;
        __half2 hv; hv.x = __float2half_rn(z0); hv.y = __float2half_rn(z1);
        *(__half2*)(g_zh + dst) = hv;
    }
}

// ---------------- launch ----------------
extern "C" void kernel_launch(void* const* d_in, const int* in_sizes, int n_in,
                              void* d_out, int out_size)
{
    const float* x    = (const float*)d_in[0];
    const float* rope = (const float*)d_in[1];
    const float* Waq  = (const float*)d_in[2];
    const float* baq  = (const float*)d_in[3];
    const float* Wbq  = (const float*)d_in[4];
    const float* bbq  = (const float*)d_in[5];
    const float* Wak  = (const float*)d_in[6];
    const float* bak  = (const float*)d_in[7];
    const float* Wbk  = (const float*)d_in[8];
    const float* bbk  = (const float*)d_in[9];
    const float* Wav  = (const float*)d_in[10];
    const float* bav  = (const float*)d_in[11];
    const float* Wbv  = (const float*)d_in[12];
    const float* bbv  = (const float*)d_in[13];
    const float* Wout = (const float*)d_in[14];
    const float* bout = (const float*)d_in[15];

    void *p_xhi, *p_Y, *p_zh, *p_W1hi, *p_Wohi, *p_b1;
    cudaGetSymbolAddress(&p_xhi,  g_xhi);
    cudaGetSymbolAddress(&p_Y,    g_Y);
    cudaGetSymbolAddress(&p_zh,   g_zh);
    cudaGetSymbolAddress(&p_W1hi, g_W1hi);
    cudaGetSymbolAddress(&p_Wohi, g_Wohi);
    cudaGetSymbolAddress(&p_b1,   g_b1);

    cudaFuncSetAttribute(k_gemm, cudaFuncAttributeMaxDynamicSharedMemorySize, SMEM_GEMM);

    // fused weight pack + x conversion (writes xhi ascending; tail stays in L2)
    k_prep<<<PACK_BLOCKS + CONV_BLOCKS, 256>>>(x, Waq,Wbq,Wak,Wbk,Wav,Wbv,
                                               baq,bbq,bak,bbk,bav,bbv, Wout);

    // stage 1: Y = x_h @ W1_h + b1   (m reversed: reads xhi tail first)
    k_gemm<<<dim3(6,256), 512, SMEM_GEMM>>>((const __half*)p_xhi, (const __half*)p_W1hi,
                                            (const float*)p_b1, (float*)p_Y);

    // middle ascending: reads the low-m Y that gemm1 (reversed) wrote last
    k_middle<<<NTOK/8, 256>>>(rope);

    // stage 2: out = z @ Wout_h + b_out   (m reversed: reads zh tail first)
    k_gemm<<<dim3(6,256), 512, SMEM_GEMM>>>((const __half*)p_zh, (const __half*)p_Wohi,
                                            bout, (float*)d_out);
}